// round 2
// baseline (speedup 1.0000x reference)
#include <cuda_runtime.h>
#include <math.h>

// ---------------------------------------------------------------------------
// Problem constants
// ---------------------------------------------------------------------------
namespace {
constexpr int B   = 128;
constexpr int T   = 31;
constexpr int TP1 = 32;     // T+1
constexpr int E   = 512;
constexpr int H   = 512;
constexpr int V   = 10000;
constexpr int A   = 2048;
constexpr int G4  = 2048;   // 4*H

// scratch layout (floats) inside one __device__ buffer
constexpr size_t XS_OFF   = 0;                           // [TP1][B][E]
constexpr size_t H_OFF    = XS_OFF   + (size_t)TP1*B*E;  // [B][H]
constexpr size_t C_OFF    = H_OFF    + (size_t)B*H;      // [B][H]
constexpr size_t HID_OFF  = C_OFF    + (size_t)B*H;      // [TP1][B][H]
constexpr size_t SC_OFF   = HID_OFF  + (size_t)TP1*B*H;  // [B][A] attn scores
constexpr size_t AT_OFF   = SC_OFF   + (size_t)B*A;      // [B][A] attended
constexpr size_t X2_OFF   = AT_OFF   + (size_t)B*A;      // [B][E]
constexpr size_t GA_OFF   = X2_OFF   + (size_t)B*E;      // [B][G4] gates
constexpr size_t WG_OFF   = GA_OFF   + (size_t)B*G4;     // [G4][E+H] fused W_ih|W_hh
constexpr size_t BS_OFF   = WG_OFF   + (size_t)G4*(E+H); // [G4] b_ih+b_hh
constexpr size_t PART_OFF = BS_OFF   + (size_t)G4;       // [4][B][E] splitK partials
constexpr size_t BUF_TOTAL = PART_OFF + (size_t)4*B*E;
}

__device__ float g_buf[BUF_TOTAL];

// ---------------------------------------------------------------------------
// Packed f32x2 FMA helpers (sm_103a): 2x fp32 MAC per fma-pipe instruction
// ---------------------------------------------------------------------------
typedef unsigned long long ull;

__device__ __forceinline__ ull ffma2(ull a, ull b, ull c) {
    ull d;
    asm("fma.rn.f32x2 %0, %1, %2, %3;" : "=l"(d) : "l"(a), "l"(b), "l"(c));
    return d;
}
__device__ __forceinline__ ull dup2(float x) {
    ull d;
    asm("mov.b64 %0, {%1, %1};" : "=l"(d) : "f"(x));
    return d;
}
__device__ __forceinline__ float2 unpk(ull v) {
    float2 r;
    asm("mov.b64 {%0, %1}, %2;" : "=f"(r.x), "=f"(r.y) : "l"(v));
    return r;
}

// ---------------------------------------------------------------------------
// Dual-input tiled SGEMM:  C[M,N] = A1[M,K1] @ W[:, :K1]^T
//                                 + A2[M,K2] @ W[:, K1:]^T  (+ bias)
// W is [N, K1+K2] row-major, leading dim ldw. Optional split-K via gridDim.z:
// each z-slice handles KC of the K range and writes its own [M,N] slab of C.
// TN fixed at 4; accumulators packed pairwise along TM with fma.rn.f32x2.
// ---------------------------------------------------------------------------
template<int BM, int BN, int BK, int TM>
__global__ void __launch_bounds__((BM/TM)*(BN/4))
sgemm_dual(float* __restrict__ C, int ldc,
           const float* __restrict__ A1, int lda1, int K1,
           const float* __restrict__ A2, int lda2, int K2,
           const float* __restrict__ W,  int ldw,
           const float* __restrict__ bias,
           int M, int N, int KC)
{
    constexpr int TN = 4;
    constexpr int THREADS = (BM/TM)*(BN/TN);
    __shared__ float As[BK][BM];   // transposed A tile
    __shared__ float Ws[BK][BN];   // transposed W tile

    const int tid  = threadIdx.x;
    const int tn   = tid % (BN/TN);
    const int tm   = tid / (BN/TN);
    const int row0 = blockIdx.y * BM;
    const int col0 = blockIdx.x * BN;
    const int K    = K1 + K2;
    const int kbeg = blockIdx.z * KC;
    const int kend = (kbeg + KC < K) ? (kbeg + KC) : K;
    float* Cz = C + (size_t)blockIdx.z * M * N;

    ull acc[TM/2][TN];
#pragma unroll
    for (int i = 0; i < TM/2; ++i)
#pragma unroll
        for (int j = 0; j < TN; ++j) acc[i][j] = 0ULL;

    for (int k0 = kbeg; k0 < kend; k0 += BK) {
        const float* Ap; int lda; int kk;
        if (k0 < K1) { Ap = A1; lda = lda1; kk = k0; }
        else         { Ap = A2; lda = lda2; kk = k0 - K1; }

        // load A tile (BM x BK) as float4, store transposed
        for (int i = tid; i < BM*(BK/4); i += THREADS) {
            int m  = i / (BK/4);
            int kq = i % (BK/4);
            int gm = row0 + m;
            float4 v = make_float4(0.f, 0.f, 0.f, 0.f);
            if (gm < M)
                v = *reinterpret_cast<const float4*>(Ap + (size_t)gm*lda + kk + kq*4);
            As[kq*4+0][m] = v.x; As[kq*4+1][m] = v.y;
            As[kq*4+2][m] = v.z; As[kq*4+3][m] = v.w;
        }
        // load W tile (BN x BK) as float4, store transposed
        for (int i = tid; i < BN*(BK/4); i += THREADS) {
            int n  = i / (BK/4);
            int kq = i % (BK/4);
            int gn = col0 + n;
            float4 v = make_float4(0.f, 0.f, 0.f, 0.f);
            if (gn < N)
                v = *reinterpret_cast<const float4*>(W + (size_t)gn*ldw + k0 + kq*4);
            Ws[kq*4+0][n] = v.x; Ws[kq*4+1][n] = v.y;
            Ws[kq*4+2][n] = v.z; Ws[kq*4+3][n] = v.w;
        }
        __syncthreads();

#pragma unroll
        for (int k = 0; k < BK; ++k) {
            ull a2[TM/2];
            const ulonglong2* ap =
                reinterpret_cast<const ulonglong2*>(&As[k][tm*TM]);
#pragma unroll
            for (int i = 0; i < TM/4; ++i) {
                ulonglong2 p = ap[i];
                a2[2*i]   = p.x;
                a2[2*i+1] = p.y;
            }
            float4 wv = *reinterpret_cast<const float4*>(&Ws[k][tn*TN]);
            ull w0 = dup2(wv.x), w1 = dup2(wv.y), w2 = dup2(wv.z), w3 = dup2(wv.w);
#pragma unroll
            for (int i = 0; i < TM/2; ++i) {
                acc[i][0] = ffma2(a2[i], w0, acc[i][0]);
                acc[i][1] = ffma2(a2[i], w1, acc[i][1]);
                acc[i][2] = ffma2(a2[i], w2, acc[i][2]);
                acc[i][3] = ffma2(a2[i], w3, acc[i][3]);
            }
        }
        __syncthreads();
    }

    // epilogue
    const int cc = col0 + tn*TN;
    float bv[TN];
#pragma unroll
    for (int j = 0; j < TN; ++j) {
        int cj = cc + j;
        bv[j] = (bias != nullptr && cj < N) ? bias[cj] : 0.f;
    }
#pragma unroll
    for (int i = 0; i < TM/2; ++i) {
        float2 u[TN];
#pragma unroll
        for (int j = 0; j < TN; ++j) u[j] = unpk(acc[i][j]);
#pragma unroll
        for (int rr = 0; rr < 2; ++rr) {
            int r = row0 + tm*TM + 2*i + rr;
            if (r >= M) continue;
            float vals[TN];
#pragma unroll
            for (int j = 0; j < TN; ++j)
                vals[j] = (rr == 0 ? u[j].x : u[j].y) + bv[j];
            float* cp = Cz + (size_t)r*ldc + cc;
            if (cc + 3 < N) {
                *reinterpret_cast<float4*>(cp) =
                    make_float4(vals[0], vals[1], vals[2], vals[3]);
            } else {
#pragma unroll
                for (int j = 0; j < TN; ++j)
                    if (cc + j < N) cp[j] = vals[j];
            }
        }
    }
}

// ---------------------------------------------------------------------------
// Prep: zero h/c, fuse biases, fuse W_ih|W_hh into Wg[G4][E+H]
// ---------------------------------------------------------------------------
__global__ void k_prep(const float* __restrict__ b_ih, const float* __restrict__ b_hh,
                       const float* __restrict__ W_ih, const float* __restrict__ W_hh)
{
    int idx = blockIdx.x * blockDim.x + threadIdx.x;
    int stride = gridDim.x * blockDim.x;
    for (int i = idx; i < B*H; i += stride) {
        g_buf[H_OFF + i] = 0.f;
        g_buf[C_OFF + i] = 0.f;
    }
    for (int i = idx; i < G4; i += stride)
        g_buf[BS_OFF + i] = b_ih[i] + b_hh[i];
    for (int i = idx; i < G4*(E+H); i += stride) {
        int n = i >> 10;          // /(E+H) = 1024
        int k = i & 1023;
        g_buf[WG_OFF + i] = (k < E) ? W_ih[n*E + k] : W_hh[n*H + (k - E)];
    }
}

// xs[0] = features; xs[t] = embed_table[captions[:, t-1]]
__global__ void k_build_xs(const float* __restrict__ features,
                           const int*   __restrict__ captions,
                           const float* __restrict__ embed)
{
    int idx = blockIdx.x * blockDim.x + threadIdx.x;
    int stride = gridDim.x * blockDim.x;
    for (int i = idx; i < TP1*B*E; i += stride) {
        int e  = i & (E - 1);
        int be = i >> 9;          // /E
        int b  = be & (B - 1);
        int t  = be >> 7;         // /B
        float v;
        if (t == 0) {
            v = features[b*E + e];
        } else {
            int tok = captions[b*T + (t - 1)];
            v = embed[(size_t)tok*E + e];
        }
        g_buf[XS_OFF + i] = v;
    }
}

// ---------------------------------------------------------------------------
// Per-row softmax over A=2048 scores (already include b_attn), then
// attended = cnn * softmax. One block per batch row, 256 threads x 8 elems.
// ---------------------------------------------------------------------------
__global__ void __launch_bounds__(256)
k_softmax_att(const float* __restrict__ scores,
              const float* __restrict__ cnn,
              float* __restrict__ att)
{
    int b = blockIdx.x;
    int t = threadIdx.x;
    const float* s = scores + (size_t)b*A;
    float v[8];
    float mx = -1e30f;
#pragma unroll
    for (int i = 0; i < 8; ++i) {
        v[i] = s[t + 256*i];
        mx = fmaxf(mx, v[i]);
    }
    __shared__ float red[256];
    red[t] = mx; __syncthreads();
    for (int off = 128; off > 0; off >>= 1) {
        if (t < off) red[t] = fmaxf(red[t], red[t + off]);
        __syncthreads();
    }
    mx = red[0]; __syncthreads();

    float sum = 0.f;
#pragma unroll
    for (int i = 0; i < 8; ++i) {
        v[i] = expf(v[i] - mx);
        sum += v[i];
    }
    red[t] = sum; __syncthreads();
    for (int off = 128; off > 0; off >>= 1) {
        if (t < off) red[t] += red[t + off];
        __syncthreads();
    }
    float inv = 1.f / red[0];

    const float* cb = cnn + (size_t)b*A;
    float* ab = att + (size_t)b*A;
#pragma unroll
    for (int i = 0; i < 8; ++i)
        ab[t + 256*i] = cb[t + 256*i] * v[i] * inv;
}

// reduce 4 split-K partials + bias -> x2
__global__ void k_reduce4(const float* __restrict__ part,
                          const float* __restrict__ bias,
                          float* __restrict__ out, int MN, int N)
{
    int i = blockIdx.x * blockDim.x + threadIdx.x;
    if (i < MN) {
        float s = part[i] + part[i + MN] + part[i + 2*MN] + part[i + 3*MN];
        out[i] = s + bias[i % N];
    }
}

// ---------------------------------------------------------------------------
// LSTM pointwise: gates [B, 4H] (order i,f,g,o) -> new h,c; h also written to
// hidden row block (packed order row = t*B + b).
// ---------------------------------------------------------------------------
__global__ void k_lstm(const float* __restrict__ gates,
                       float* __restrict__ h, float* __restrict__ c,
                       float* __restrict__ hid)
{
    int idx = blockIdx.x * blockDim.x + threadIdx.x;
    if (idx >= B*H) return;
    int b = idx >> 9;       // /H
    int j = idx & (H - 1);
    const float* g = gates + (size_t)b*G4;
    float ig = 1.f / (1.f + expf(-g[j]));
    float fg = 1.f / (1.f + expf(-g[j + H]));
    float gg = tanhf(g[j + 2*H]);
    float og = 1.f / (1.f + expf(-g[j + 3*H]));
    float cn = fg * c[idx] + ig * gg;
    float hn = og * tanhf(cn);
    c[idx] = cn;
    h[idx] = hn;
    hid[idx] = hn;
}

// ---------------------------------------------------------------------------
// Host launch sequence (graph-capturable: kernel launches only)
// ---------------------------------------------------------------------------
extern "C" void kernel_launch(void* const* d_in, const int* in_sizes, int n_in,
                              void* d_out, int out_size)
{
    const float* features = (const float*)d_in[0];
    const float* cnn      = (const float*)d_in[1];
    const int*   captions = (const int*)  d_in[2];
    /* d_in[3] = lengths (unused: all T+1) */
    const float* embed    = (const float*)d_in[4];
    const float* W_ih     = (const float*)d_in[5];
    const float* W_hh     = (const float*)d_in[6];
    const float* b_ih     = (const float*)d_in[7];
    const float* b_hh     = (const float*)d_in[8];
    const float* W_attn   = (const float*)d_in[9];
    const float* b_attn   = (const float*)d_in[10];
    const float* W_attd   = (const float*)d_in[11];
    const float* b_attd   = (const float*)d_in[12];
    const float* W_out    = (const float*)d_in[13];
    const float* b_out    = (const float*)d_in[14];
    float* out = (float*)d_out;

    float* buf = nullptr;
    cudaGetSymbolAddress((void**)&buf, g_buf);

    float* xs    = buf + XS_OFF;
    float* hbuf  = buf + H_OFF;
    float* cbuf  = buf + C_OFF;
    float* hid   = buf + HID_OFF;
    float* sc    = buf + SC_OFF;
    float* at    = buf + AT_OFF;
    float* x2    = buf + X2_OFF;
    float* gates = buf + GA_OFF;
    float* Wg    = buf + WG_OFF;
    float* bsum  = buf + BS_OFF;
    float* part  = buf + PART_OFF;

    // prep
    k_prep<<<2048, 256>>>(b_ih, b_hh, W_ih, W_hh);
    k_build_xs<<<2048, 256>>>(features, captions, embed);

    const dim3 gGate(G4 / 64, B / 32, 1);   // 32 x 4 blocks
    const dim3 gAttn(A  / 64, B / 32, 1);   // 32 x 4 blocks
    const dim3 gAttd(E  / 64, B / 32, 4);   // 8 x 4 x 4 blocks, splitK=4
    const int  KC_ATTD = (E + A) / 4;       // 640, multiple of BK

    // t = 0: plain LSTM step from zero state (h buffer is zeroed)
    sgemm_dual<32, 64, 16, 4><<<gGate, 128>>>(
        gates, G4, xs, E, E, hbuf, H, H, Wg, E + H, bsum, B, G4, E + H);
    k_lstm<<<(B*H + 255)/256, 256>>>(gates, hbuf, cbuf, hid);

    // t = 1..T: attention + LSTM
    for (int t = 1; t <= T; ++t) {
        const float* xt = xs + (size_t)t * B * E;

        // scores = [x_t | h] @ W_attn^T + b_attn
        sgemm_dual<32, 64, 16, 4><<<gAttn, 128>>>(
            sc, A, xt, E, E, hbuf, H, H, W_attn, E + H, b_attn, B, A, E + H);

        // softmax + attended = cnn * aw
        k_softmax_att<<<B, 256>>>(sc, cnn, at);

        // x2 = [x_t | attended] @ W_attd^T + b_attd (split-K=4 + reduce)
        sgemm_dual<32, 64, 16, 4><<<gAttd, 128>>>(
            part, E, xt, E, E, at, A, A, W_attd, E + A, nullptr, B, E, KC_ATTD);
        k_reduce4<<<(B*E + 255)/256, 256>>>(part, b_attd, x2, B*E, E);

        // gates = [x2 | h] @ [W_ih|W_hh]^T + (b_ih + b_hh)
        sgemm_dual<32, 64, 16, 4><<<gGate, 128>>>(
            gates, G4, x2, E, E, hbuf, H, H, Wg, E + H, bsum, B, G4, E + H);

        // pointwise LSTM; h written into hidden row block t
        k_lstm<<<(B*H + 255)/256, 256>>>(gates, hbuf, cbuf,
                                         hid + (size_t)t * B * H);
    }

    // logits = hidden[4096, 512] @ W_out^T + b_out  -> out [4096, 10000]
    const dim3 gOut((V + 63) / 64, (TP1 * B) / 64, 1);  // 157 x 64
    sgemm_dual<64, 64, 16, 8><<<gOut, 128>>>(
        out, V, hid, H, H, hid, H, 0, W_out, H, b_out, TP1 * B, V, H);
}

// round 3
// speedup vs baseline: 2.6690x; 2.6690x over previous
#include <cuda_runtime.h>
#include <math.h>

// ---------------------------------------------------------------------------
// Problem constants
// ---------------------------------------------------------------------------
namespace {
constexpr int B   = 128;
constexpr int T   = 31;
constexpr int TP1 = 32;     // T+1
constexpr int E   = 512;
constexpr int H   = 512;
constexpr int V   = 10000;
constexpr int A   = 2048;
constexpr int G4  = 2048;   // 4*H

// scratch layout (floats) inside one __device__ buffer
constexpr size_t XS_OFF   = 0;                              // [TP1][B][E]
constexpr size_t PAN_OFF  = XS_OFF  + (size_t)TP1*B*E;      // [TP1][B][A] pre attn (x part + b_attn)
constexpr size_t PAD_OFF  = PAN_OFF + (size_t)TP1*B*A;      // [TP1][B][E] pre attd (x part + b_attd)
constexpr size_t HID_OFF  = PAD_OFF + (size_t)TP1*B*E;      // [TP1][B][H]
constexpr size_t H_OFF    = HID_OFF + (size_t)TP1*B*H;      // [B][H]
constexpr size_t C_OFF    = H_OFF   + (size_t)B*H;          // [B][H]
constexpr size_t ATT_OFF  = C_OFF   + (size_t)B*H;          // [B][A]
constexpr size_t X2_OFF   = ATT_OFF + (size_t)B*A;          // [B][E]
constexpr size_t SLA_OFF  = X2_OFF  + (size_t)B*E;          // [4][B][A] attn splitK slabs
constexpr size_t SLD_OFF  = SLA_OFF + (size_t)4*B*A;        // [8][B][E] attd splitK slabs
constexpr size_t SLG_OFF  = SLD_OFF + (size_t)8*B*E;        // [4][B][G4] gate splitK slabs
constexpr size_t WG_OFF   = SLG_OFF + (size_t)4*B*G4;       // [G4][E+H] fused W_ih|W_hh
constexpr size_t BS_OFF   = WG_OFF  + (size_t)G4*(E+H);     // [G4] b_ih+b_hh
constexpr size_t BUF_TOTAL = BS_OFF + (size_t)G4;
}

__device__ float g_buf[BUF_TOTAL];

// ---------------------------------------------------------------------------
// Packed f32x2 FMA helpers (sm_103a)
// ---------------------------------------------------------------------------
typedef unsigned long long ull;

__device__ __forceinline__ ull ffma2(ull a, ull b, ull c) {
    ull d;
    asm("fma.rn.f32x2 %0, %1, %2, %3;" : "=l"(d) : "l"(a), "l"(b), "l"(c));
    return d;
}
__device__ __forceinline__ ull dup2(float x) {
    ull d;
    asm("mov.b64 %0, {%1, %1};" : "=l"(d) : "f"(x));
    return d;
}
__device__ __forceinline__ float2 unpk(ull v) {
    float2 r;
    asm("mov.b64 {%0, %1}, %2;" : "=f"(r.x), "=f"(r.y) : "l"(v));
    return r;
}

// ---------------------------------------------------------------------------
// Pipelined dual-input SGEMM: C = [A1|A2] @ W^T (+bias), split-K via gridDim.z
// - register-prefetch double-buffered shared tiles, BK=32
// - transposed smem with XOR swizzle j ^= (k>>2)&7 : conflict-free stores+loads
// - fp32x2 packed FMAs, accumulators packed pairwise along M
// Requirements: K1, K2, KC multiples of BK; lda/ldw rows 16B aligned; TN==4.
// ---------------------------------------------------------------------------
template<int BM, int BN, int BK, int TM>
__global__ void __launch_bounds__((BM/TM)*(BN/4))
sgemm_pipe(float* __restrict__ C, int ldc,
           const float* __restrict__ A1, int lda1, int K1,
           const float* __restrict__ A2, int lda2, int K2,
           const float* __restrict__ W,  int ldw,
           const float* __restrict__ bias,
           int M, int N, int KC)
{
    constexpr int TN = 4;
    constexpr int THREADS = (BM/TM)*(BN/TN);
    constexpr int BMq = BM/4, BNq = BN/4, BKq = BK/4;
    constexpr int NA = (BM*BKq)/THREADS;   // float4 loads/thread for A tile
    constexpr int NW = (BN*BKq)/THREADS;   // float4 loads/thread for W tile

    __shared__ float4 As[2][BK][BMq];
    __shared__ float4 Ws[2][BK][BNq];

    const int tid  = threadIdx.x;
    const int tn   = tid % (BN/TN);
    const int tm   = tid / (BN/TN);
    const int row0 = blockIdx.y * BM;
    const int col0 = blockIdx.x * BN;
    const int K    = K1 + K2;
    const int kbeg = blockIdx.z * KC;
    const int kend = (kbeg + KC < K) ? (kbeg + KC) : K;
    const int ntile = (kend - kbeg) / BK;
    float* Cz = C + (size_t)blockIdx.z * M * N;

    ull acc[TM/2][TN];
#pragma unroll
    for (int i = 0; i < TM/2; ++i)
#pragma unroll
        for (int j = 0; j < TN; ++j) acc[i][j] = 0ULL;

    float4 ra[NA], rw[NW];

    auto LOADT = [&](int t) {
        const int k0 = kbeg + t * BK;
        const float* Ap; int lda; int kk;
        if (k0 < K1) { Ap = A1; lda = lda1; kk = k0; }
        else         { Ap = A2; lda = lda2; kk = k0 - K1; }
#pragma unroll
        for (int i = 0; i < NA; ++i) {
            int idx = tid + i * THREADS;
            int m = idx / BKq, kq = idx % BKq;
            int gm = row0 + m;
            ra[i] = (gm < M)
                ? *reinterpret_cast<const float4*>(Ap + (size_t)gm*lda + kk + kq*4)
                : make_float4(0.f, 0.f, 0.f, 0.f);
        }
#pragma unroll
        for (int i = 0; i < NW; ++i) {
            int idx = tid + i * THREADS;
            int n = idx / BKq, kq = idx % BKq;
            int gn = col0 + n;
            rw[i] = (gn < N)
                ? *reinterpret_cast<const float4*>(W + (size_t)gn*ldw + k0 + kq*4)
                : make_float4(0.f, 0.f, 0.f, 0.f);
        }
    };

    auto STORET = [&](int bsel) {
#pragma unroll
        for (int i = 0; i < NA; ++i) {
            int idx = tid + i * THREADS;
            int m = idx / BKq, kq = idx % BKq;
            const float* pv = reinterpret_cast<const float*>(&ra[i]);
#pragma unroll
            for (int r = 0; r < 4; ++r) {
                int k = kq*4 + r;
                int j = (m >> 2) ^ kq;           // (k>>2)&7 == kq (BK=32)
                reinterpret_cast<float*>(&As[bsel][k][j])[m & 3] = pv[r];
            }
        }
#pragma unroll
        for (int i = 0; i < NW; ++i) {
            int idx = tid + i * THREADS;
            int n = idx / BKq, kq = idx % BKq;
            const float* pv = reinterpret_cast<const float*>(&rw[i]);
#pragma unroll
            for (int r = 0; r < 4; ++r) {
                int k = kq*4 + r;
                int j = (n >> 2) ^ kq;
                reinterpret_cast<float*>(&Ws[bsel][k][j])[n & 3] = pv[r];
            }
        }
    };

    auto COMP = [&](int bsel) {
#pragma unroll
        for (int k = 0; k < BK; ++k) {
            const int s = (k >> 2) & 7;
            ull a2[TM/2];
#pragma unroll
            for (int q = 0; q < TM/4; ++q) {
                ulonglong2 p = *reinterpret_cast<const ulonglong2*>(
                    &As[bsel][k][(tm*(TM/4) + q) ^ s]);
                a2[2*q]   = p.x;
                a2[2*q+1] = p.y;
            }
            float4 wv = Ws[bsel][k][tn ^ s];
            ull w0 = dup2(wv.x), w1 = dup2(wv.y), w2 = dup2(wv.z), w3 = dup2(wv.w);
#pragma unroll
            for (int i = 0; i < TM/2; ++i) {
                acc[i][0] = ffma2(a2[i], w0, acc[i][0]);
                acc[i][1] = ffma2(a2[i], w1, acc[i][1]);
                acc[i][2] = ffma2(a2[i], w2, acc[i][2]);
                acc[i][3] = ffma2(a2[i], w3, acc[i][3]);
            }
        }
    };

    if (ntile > 0) {
        LOADT(0);
        STORET(0);
        __syncthreads();
        for (int t = 0; t < ntile; ++t) {
            if (t + 1 < ntile) LOADT(t + 1);
            COMP(t & 1);
            if (t + 1 < ntile) {
                __syncthreads();
                STORET((t + 1) & 1);
                __syncthreads();
            }
        }
    }

    // epilogue
    const int cc = col0 + tn*TN;
    float bv[TN];
#pragma unroll
    for (int j = 0; j < TN; ++j) {
        int cj = cc + j;
        bv[j] = (bias != nullptr && cj < N) ? bias[cj] : 0.f;
    }
#pragma unroll
    for (int i = 0; i < TM/2; ++i) {
        float2 u[TN];
#pragma unroll
        for (int j = 0; j < TN; ++j) u[j] = unpk(acc[i][j]);
#pragma unroll
        for (int rr = 0; rr < 2; ++rr) {
            int r = row0 + tm*TM + 2*i + rr;
            if (r >= M) continue;
            float vals[TN];
#pragma unroll
            for (int j = 0; j < TN; ++j)
                vals[j] = (rr == 0 ? u[j].x : u[j].y) + bv[j];
            float* cp = Cz + (size_t)r*ldc + cc;
            if (cc + 3 < N) {
                *reinterpret_cast<float4*>(cp) =
                    make_float4(vals[0], vals[1], vals[2], vals[3]);
            } else {
#pragma unroll
                for (int j = 0; j < TN; ++j)
                    if (cc + j < N) cp[j] = vals[j];
            }
        }
    }
}

// ---------------------------------------------------------------------------
// Prep: zero h/c, fuse biases, fuse W_ih|W_hh into Wg[G4][E+H]
// ---------------------------------------------------------------------------
__global__ void k_prep(const float* __restrict__ b_ih, const float* __restrict__ b_hh,
                       const float* __restrict__ W_ih, const float* __restrict__ W_hh)
{
    int idx = blockIdx.x * blockDim.x + threadIdx.x;
    int stride = gridDim.x * blockDim.x;
    for (int i = idx; i < B*H; i += stride) {
        g_buf[H_OFF + i] = 0.f;
        g_buf[C_OFF + i] = 0.f;
    }
    for (int i = idx; i < G4; i += stride)
        g_buf[BS_OFF + i] = b_ih[i] + b_hh[i];
    for (int i = idx; i < G4*(E+H); i += stride) {
        int n = i >> 10;          // /(E+H) = 1024
        int k = i & 1023;
        g_buf[WG_OFF + i] = (k < E) ? W_ih[n*E + k] : W_hh[n*H + (k - E)];
    }
}

// xs[0] = features; xs[t] = embed_table[captions[:, t-1]]
__global__ void k_build_xs(const float* __restrict__ features,
                           const int*   __restrict__ captions,
                           const float* __restrict__ embed)
{
    int idx = blockIdx.x * blockDim.x + threadIdx.x;
    int stride = gridDim.x * blockDim.x;
    for (int i = idx; i < TP1*B*E; i += stride) {
        int e  = i & (E - 1);
        int be = i >> 9;          // /E
        int b  = be & (B - 1);
        int t  = be >> 7;         // /B
        float v;
        if (t == 0) {
            v = features[b*E + e];
        } else {
            int tok = captions[b*T + (t - 1)];
            v = embed[(size_t)tok*E + e];
        }
        g_buf[XS_OFF + i] = v;
    }
}

// ---------------------------------------------------------------------------
// softmax(pre + 4 splitK slabs) * cnn -> att. One block per batch row.
// ---------------------------------------------------------------------------
__global__ void __launch_bounds__(256)
k_softmax_att(const float* __restrict__ pre,
              const float* __restrict__ slab,
              const float* __restrict__ cnn,
              float* __restrict__ att)
{
    int b = blockIdx.x;
    int t = threadIdx.x;
    const size_t o0 = (size_t)b*A;
    const size_t BA = (size_t)B*A;
    float v[8];
    float mx = -1e30f;
#pragma unroll
    for (int i = 0; i < 8; ++i) {
        size_t o = o0 + t + 256*i;
        float s = pre[o] + slab[o] + slab[o + BA] + slab[o + 2*BA] + slab[o + 3*BA];
        v[i] = s;
        mx = fmaxf(mx, s);
    }
    __shared__ float red[256];
    red[t] = mx; __syncthreads();
    for (int off = 128; off > 0; off >>= 1) {
        if (t < off) red[t] = fmaxf(red[t], red[t + off]);
        __syncthreads();
    }
    mx = red[0]; __syncthreads();

    float sum = 0.f;
#pragma unroll
    for (int i = 0; i < 8; ++i) {
        v[i] = expf(v[i] - mx);
        sum += v[i];
    }
    red[t] = sum; __syncthreads();
    for (int off = 128; off > 0; off >>= 1) {
        if (t < off) red[t] += red[t + off];
        __syncthreads();
    }
    float inv = 1.f / red[0];

    const float* cb = cnn + o0;
    float* ab = att + o0;
#pragma unroll
    for (int i = 0; i < 8; ++i)
        ab[t + 256*i] = cb[t + 256*i] * v[i] * inv;
}

// x2 = pre_attd[t] + sum of 8 splitK slabs
__global__ void k_reduce_attd(const float* __restrict__ pre,
                              const float* __restrict__ slab,
                              float* __restrict__ x2)
{
    int i = blockIdx.x * blockDim.x + threadIdx.x;
    if (i < B*E) {
        float s = pre[i];
#pragma unroll
        for (int z = 0; z < 8; ++z) s += slab[i + (size_t)z*B*E];
        x2[i] = s;
    }
}

// LSTM pointwise fused with 4-slab gate reduction + bias
__global__ void k_lstm_red(const float* __restrict__ sl,
                           const float* __restrict__ bsum,
                           float* __restrict__ h, float* __restrict__ c,
                           float* __restrict__ hid)
{
    int idx = blockIdx.x * blockDim.x + threadIdx.x;
    if (idx >= B*H) return;
    int b = idx >> 9;       // /H
    int j = idx & (H - 1);
    float gi = bsum[j], gf = bsum[j + H], gg = bsum[j + 2*H], go = bsum[j + 3*H];
#pragma unroll
    for (int z = 0; z < 4; ++z) {
        const float* g = sl + (size_t)z*B*G4 + (size_t)b*G4;
        gi += g[j]; gf += g[j + H]; gg += g[j + 2*H]; go += g[j + 3*H];
    }
    float ig = 1.f / (1.f + expf(-gi));
    float fg = 1.f / (1.f + expf(-gf));
    float gt = tanhf(gg);
    float og = 1.f / (1.f + expf(-go));
    float cn = fg * c[idx] + ig * gt;
    float hn = og * tanhf(cn);
    c[idx] = cn;
    h[idx] = hn;
    hid[idx] = hn;
}

// ---------------------------------------------------------------------------
// Host launch sequence (graph-capturable: kernel launches only)
// ---------------------------------------------------------------------------
extern "C" void kernel_launch(void* const* d_in, const int* in_sizes, int n_in,
                              void* d_out, int out_size)
{
    const float* features = (const float*)d_in[0];
    const float* cnn      = (const float*)d_in[1];
    const int*   captions = (const int*)  d_in[2];
    /* d_in[3] = lengths (unused: all T+1) */
    const float* embed    = (const float*)d_in[4];
    const float* W_ih     = (const float*)d_in[5];
    const float* W_hh     = (const float*)d_in[6];
    const float* b_ih     = (const float*)d_in[7];
    const float* b_hh     = (const float*)d_in[8];
    const float* W_attn   = (const float*)d_in[9];
    const float* b_attn   = (const float*)d_in[10];
    const float* W_attd   = (const float*)d_in[11];
    const float* b_attd   = (const float*)d_in[12];
    const float* W_out    = (const float*)d_in[13];
    const float* b_out    = (const float*)d_in[14];
    float* out = (float*)d_out;

    float* buf = nullptr;
    cudaGetSymbolAddress((void**)&buf, g_buf);

    float* xs    = buf + XS_OFF;
    float* pan   = buf + PAN_OFF;
    float* pad   = buf + PAD_OFF;
    float* hid   = buf + HID_OFF;
    float* hbuf  = buf + H_OFF;
    float* cbuf  = buf + C_OFF;
    float* att   = buf + ATT_OFF;
    float* x2    = buf + X2_OFF;
    float* slA   = buf + SLA_OFF;
    float* slD   = buf + SLD_OFF;
    float* slG   = buf + SLG_OFF;
    float* Wg    = buf + WG_OFF;
    float* bsum  = buf + BS_OFF;

    // prep
    k_prep<<<2048, 256>>>(b_ih, b_hh, W_ih, W_hh);
    k_build_xs<<<2048, 256>>>(features, captions, embed);

    const int MALL = TP1 * B;  // 4096

    // precompute x-dependent projections for ALL timesteps (parallel, efficient)
    // pan[t] = x_t @ W_attn[:, :E]^T + b_attn   -> [4096, 2048]
    sgemm_pipe<64, 64, 32, 8><<<dim3(A/64, MALL/64, 1), 128>>>(
        pan, A, xs, E, E, nullptr, 0, 0, W_attn, E + H, b_attn, MALL, A, E);
    // pad[t] = x_t @ W_attd[:, :E]^T + b_attd   -> [4096, 512]
    sgemm_pipe<64, 64, 32, 8><<<dim3(E/64, MALL/64, 1), 128>>>(
        pad, E, xs, E, E, nullptr, 0, 0, W_attd, E + A, b_attd, MALL, E, E);

    const dim3 gGate(G4/64, B/32, 4);   // splitK=4, KC=256 -> 512 blocks
    const dim3 gAttn(A /64, B/32, 4);   // splitK=4, KC=128 -> 512 blocks
    const dim3 gAttd(E /64, B/32, 8);   // splitK=8, KC=256 -> 256 blocks

    // t = 0: gates = xs0 @ W_ih^T + 0 @ W_hh^T (+bias); h is zeroed
    sgemm_pipe<32, 64, 32, 4><<<gGate, 128>>>(
        slG, G4, xs, E, E, hbuf, H, H, Wg, E + H, nullptr, B, G4, (E + H)/4);
    k_lstm_red<<<(B*H + 255)/256, 256>>>(slG, bsum, hbuf, cbuf, hid);

    // t = 1..T
    for (int t = 1; t <= T; ++t) {
        // scores_h = h @ W_attn[:, E:]^T  (splitK=4 slabs)
        sgemm_pipe<32, 64, 32, 4><<<gAttn, 128>>>(
            slA, A, hbuf, H, H, nullptr, 0, 0, W_attn + E, E + H, nullptr,
            B, A, H/4);

        // softmax(pre + slabs) * cnn
        k_softmax_att<<<B, 256>>>(pan + (size_t)t*B*A, slA, cnn, att);

        // x2_h = attended @ W_attd[:, E:]^T  (splitK=8 slabs)
        sgemm_pipe<32, 64, 32, 4><<<gAttd, 128>>>(
            slD, E, att, A, A, nullptr, 0, 0, W_attd + E, E + A, nullptr,
            B, E, A/8);
        k_reduce_attd<<<(B*E + 255)/256, 256>>>(pad + (size_t)t*B*E, slD, x2);

        // gates = [x2 | h] @ [W_ih|W_hh]^T  (splitK=4 slabs)
        sgemm_pipe<32, 64, 32, 4><<<gGate, 128>>>(
            slG, G4, x2, E, E, hbuf, H, H, Wg, E + H, nullptr, B, G4, (E + H)/4);

        // LSTM pointwise + slab reduction + bias; h -> hidden row block t
        k_lstm_red<<<(B*H + 255)/256, 256>>>(slG, bsum, hbuf, cbuf,
                                             hid + (size_t)t*B*H);
    }

    // logits = hidden[4096, 512] @ W_out^T + b_out -> out [4096, 10000]
    sgemm_pipe<64, 64, 32, 8><<<dim3((V + 63)/64, MALL/64, 1), 128>>>(
        out, V, hid, H, H, nullptr, 0, 0, W_out, H, b_out, MALL, V, H);
}

// round 5
// speedup vs baseline: 3.0914x; 1.1583x over previous
#include <cuda_runtime.h>
#include <cuda_bf16.h>
#include <math.h>
#include <stdint.h>

// ---------------------------------------------------------------------------
// Problem constants
// ---------------------------------------------------------------------------
namespace {
constexpr int B   = 128;
constexpr int T   = 31;
constexpr int TP1 = 32;     // T+1
constexpr int E   = 512;
constexpr int H   = 512;
constexpr int V   = 10000;
constexpr int A   = 2048;
constexpr int G4  = 2048;   // 4*H
constexpr int MALL = TP1 * B;   // 4096
constexpr int VPAD = 10240;     // 80 * 128
constexpr int KBF  = 1536;      // 3 * 512 split-bf16 K

// scratch layout (floats) inside one __device__ buffer
constexpr size_t XS_OFF   = 0;                              // [TP1][B][E]
constexpr size_t PAN_OFF  = XS_OFF  + (size_t)TP1*B*E;      // [TP1][B][A]
constexpr size_t PAD_OFF  = PAN_OFF + (size_t)TP1*B*A;      // [TP1][B][E]
constexpr size_t HID_OFF  = PAD_OFF + (size_t)TP1*B*E;      // [TP1][B][H]
constexpr size_t H_OFF    = HID_OFF + (size_t)TP1*B*H;      // [B][H]
constexpr size_t C_OFF    = H_OFF   + (size_t)B*H;          // [B][H]
constexpr size_t ATT_OFF  = C_OFF   + (size_t)B*H;          // [B][A]
constexpr size_t X2_OFF   = ATT_OFF + (size_t)B*A;          // [B][E]
constexpr size_t SLA_OFF  = X2_OFF  + (size_t)B*E;          // [4][B][A]
constexpr size_t SLD_OFF  = SLA_OFF + (size_t)4*B*A;        // [8][B][E]
constexpr size_t SLG_OFF  = SLD_OFF + (size_t)8*B*E;        // [4][B][G4]
constexpr size_t WG_OFF   = SLG_OFF + (size_t)4*B*G4;       // [G4][E+H]
constexpr size_t BS_OFF   = WG_OFF  + (size_t)G4*(E+H);     // [G4]
constexpr size_t BUF_TOTAL = BS_OFF + (size_t)G4;
}

__device__ float g_buf[BUF_TOTAL];

// bf16 split operand buffers
__device__ __nv_bfloat16 g_xs_bf [(size_t)MALL * KBF];
__device__ __nv_bfloat16 g_hid_bf[(size_t)MALL * KBF];
__device__ __nv_bfloat16 g_wattn_bf[(size_t)A * KBF];
__device__ __nv_bfloat16 g_wattd_bf[(size_t)E * KBF];
__device__ __nv_bfloat16 g_wout_bf[(size_t)VPAD * KBF];

// ---------------------------------------------------------------------------
// Packed f32x2 FMA helpers (sm_103a; legal PTX for compute_103)
// ---------------------------------------------------------------------------
typedef unsigned long long ull;

__device__ __forceinline__ ull ffma2(ull a, ull b, ull c) {
    ull d;
    asm("fma.rn.f32x2 %0, %1, %2, %3;" : "=l"(d) : "l"(a), "l"(b), "l"(c));
    return d;
}
__device__ __forceinline__ ull dup2(float x) {
    ull d;
    asm("mov.b64 %0, {%1, %1};" : "=l"(d) : "f"(x));
    return d;
}
__device__ __forceinline__ float2 unpk(ull v) {
    float2 r;
    asm("mov.b64 {%0, %1}, %2;" : "=f"(r.x), "=f"(r.y) : "l"(v));
    return r;
}

// ---------------------------------------------------------------------------
// HMMA helpers (sm_80+ PTX — compiles for compute_103)
// ---------------------------------------------------------------------------
__device__ __forceinline__ uint32_t smem_u32(const void* p) {
    uint32_t a;
    asm("{ .reg .u64 t; cvta.to.shared.u64 t, %1; cvt.u32.u64 %0, t; }"
        : "=r"(a) : "l"(p));
    return a;
}
__device__ __forceinline__ void cpa16(uint32_t s, const void* g) {
    asm volatile("cp.async.cg.shared.global [%0], [%1], 16;"
                 :: "r"(s), "l"(g));
}
#define CP_COMMIT() asm volatile("cp.async.commit_group;" ::: "memory")
#define CP_WAIT(N)  asm volatile("cp.async.wait_group %0;" :: "n"(N) : "memory")

#define LDSM4(R0, R1, R2, R3, ADDR) \
    asm volatile("ldmatrix.sync.aligned.m8n8.x4.shared.b16 {%0,%1,%2,%3}, [%4];" \
        : "=r"(R0), "=r"(R1), "=r"(R2), "=r"(R3) : "r"(ADDR))

__device__ __forceinline__ void mma16816(float* d, const uint32_t* a,
                                         uint32_t b0, uint32_t b1) {
    asm volatile(
        "mma.sync.aligned.m16n8k16.row.col.f32.bf16.bf16.f32 "
        "{%0,%1,%2,%3}, {%4,%5,%6,%7}, {%8,%9}, {%0,%1,%2,%3};"
        : "+f"(d[0]), "+f"(d[1]), "+f"(d[2]), "+f"(d[3])
        : "r"(a[0]), "r"(a[1]), "r"(a[2]), "r"(a[3]), "r"(b0), "r"(b1));
}

// ---------------------------------------------------------------------------
// HMMA bf16 GEMM: C[M][Nreal] (+bias) = Abf[M][1536] @ Bbf[Npad][1536]^T
// M, Npad multiples of 128; rows of Bbf beyond Nreal are zero.
// 128x128x32 tile, 256 threads, 2-stage cp.async pipeline, 80B-padded smem.
// ---------------------------------------------------------------------------
namespace {
constexpr int HBK   = 32;
constexpr int HROWB = 80;            // 40 bf16 per smem row (32 + 8 pad)
constexpr int HSTG  = 256 * HROWB;   // bytes per stage (A 128 rows + B 128 rows)
constexpr int HNT   = KBF / HBK;     // 48 k-tiles
}

__global__ void __launch_bounds__(256, 2)
hmma_gemm(float* __restrict__ C, int ldc, int Nreal,
          const __nv_bfloat16* __restrict__ Abf,
          const __nv_bfloat16* __restrict__ Bbf,
          const float* __restrict__ bias)
{
    __shared__ __align__(16) char sm[2 * HSTG];
    const uint32_t sb = smem_u32(sm);

    const int tid  = threadIdx.x;
    const int wid  = tid >> 5;
    const int lane = tid & 31;
    const int wm   = wid & 1;        // 2 warp rows  (64 rows each)
    const int wn   = wid >> 1;       // 4 warp cols  (32 cols each)
    const int row0 = blockIdx.y * 128;
    const int col0 = blockIdx.x * 128;

    // per-thread cp.async assignment: 2 A chunks + 2 B chunks of 16B
    const int qr0 = (tid)       >> 2, qc0 = (tid)       & 3;
    const int qr1 = (tid + 256) >> 2, qc1 = (tid + 256) & 3;

    auto LOADG = [&](int t, int buf) {
        const int k0 = t * HBK;
        const uint32_t sa = sb + buf * HSTG;
        const uint32_t sbm = sa + 128 * HROWB;
        cpa16(sa  + qr0 * HROWB + qc0 * 16,
              Abf + (size_t)(row0 + qr0) * KBF + k0 + qc0 * 8);
        cpa16(sa  + qr1 * HROWB + qc1 * 16,
              Abf + (size_t)(row0 + qr1) * KBF + k0 + qc1 * 8);
        cpa16(sbm + qr0 * HROWB + qc0 * 16,
              Bbf + (size_t)(col0 + qr0) * KBF + k0 + qc0 * 8);
        cpa16(sbm + qr1 * HROWB + qc1 * 16,
              Bbf + (size_t)(col0 + qr1) * KBF + k0 + qc1 * 8);
    };

    float acc[4][4][4];
#pragma unroll
    for (int i = 0; i < 4; ++i)
#pragma unroll
        for (int j = 0; j < 4; ++j)
#pragma unroll
            for (int q = 0; q < 4; ++q) acc[i][j][q] = 0.f;

    // ldmatrix lane addressing components
    const int lr = lane & 15;            // row within 16
    const int lkb = (lane >> 4) * 16;    // byte offset of 8-elem k chunk

    LOADG(0, 0);
    CP_COMMIT();

    for (int t = 0; t < HNT; ++t) {
        const int buf = t & 1;
        if (t + 1 < HNT) {
            LOADG(t + 1, buf ^ 1);
            CP_COMMIT();
            CP_WAIT(1);
        } else {
            CP_WAIT(0);
        }
        __syncthreads();

        const uint32_t aB = sb + buf * HSTG;
        const uint32_t bB = aB + 128 * HROWB;
#pragma unroll
        for (int ks = 0; ks < 2; ++ks) {
            const int kbyte = ks * 32 + lkb;
            uint32_t af[4][4];
#pragma unroll
            for (int mf = 0; mf < 4; ++mf)
                LDSM4(af[mf][0], af[mf][1], af[mf][2], af[mf][3],
                      aB + (wm * 64 + mf * 16 + lr) * HROWB + kbyte);
            uint32_t bfr[2][4];
#pragma unroll
            for (int p = 0; p < 2; ++p)
                LDSM4(bfr[p][0], bfr[p][1], bfr[p][2], bfr[p][3],
                      bB + (wn * 32 + p * 16 + lr) * HROWB + kbyte);
#pragma unroll
            for (int mf = 0; mf < 4; ++mf)
#pragma unroll
                for (int nf = 0; nf < 4; ++nf)
                    mma16816(acc[mf][nf], af[mf],
                             bfr[nf >> 1][nf & 1], bfr[nf >> 1][(nf & 1) + 2]);
        }
        __syncthreads();
    }

    // epilogue: direct stores + bias
    const int rbase = row0 + wm * 64 + (lane >> 2);
    const int cbase = col0 + wn * 32 + 2 * (lane & 3);
#pragma unroll
    for (int nf = 0; nf < 4; ++nf) {
        const int col = cbase + nf * 8;
        if (col >= Nreal) continue;
        const float2 bv = *reinterpret_cast<const float2*>(bias + col);
#pragma unroll
        for (int mf = 0; mf < 4; ++mf) {
            const int r = rbase + mf * 16;
            *reinterpret_cast<float2*>(C + (size_t)r * ldc + col) =
                make_float2(acc[mf][nf][0] + bv.x, acc[mf][nf][1] + bv.y);
            *reinterpret_cast<float2*>(C + (size_t)(r + 8) * ldc + col) =
                make_float2(acc[mf][nf][2] + bv.x, acc[mf][nf][3] + bv.y);
        }
    }
}

// ---------------------------------------------------------------------------
// fp32 -> split-bf16 conversion kernels
// A-side layout: [hi | hi | lo]; B-side layout: [hi | lo | hi]
// ---------------------------------------------------------------------------
__global__ void k_split_a(const float* __restrict__ src,
                          __nv_bfloat16* __restrict__ dst, int M)
{
    int i = blockIdx.x * blockDim.x + threadIdx.x;
    int n = M * 512;
    for (; i < n; i += gridDim.x * blockDim.x) {
        int m = i >> 9, j = i & 511;
        float x = src[i];
        __nv_bfloat16 hi = __float2bfloat16(x);
        __nv_bfloat16 lo = __float2bfloat16(x - __bfloat162float(hi));
        __nv_bfloat16* d = dst + (size_t)m * KBF;
        d[j] = hi; d[j + 512] = hi; d[j + 1024] = lo;
    }
}

__global__ void k_split_b(const float* __restrict__ src, int ld,
                          __nv_bfloat16* __restrict__ dst, int Nreal, int Npad)
{
    int i = blockIdx.x * blockDim.x + threadIdx.x;
    int n = Npad * 512;
    for (; i < n; i += gridDim.x * blockDim.x) {
        int r = i >> 9, j = i & 511;
        float x = (r < Nreal) ? src[(size_t)r * ld + j] : 0.f;
        __nv_bfloat16 hi = __float2bfloat16(x);
        __nv_bfloat16 lo = __float2bfloat16(x - __bfloat162float(hi));
        __nv_bfloat16* d = dst + (size_t)r * KBF;
        d[j] = hi; d[j + 512] = lo; d[j + 1024] = hi;
    }
}

// ---------------------------------------------------------------------------
// Pipelined dual-input fp32 SGEMM (recurrent path) — unchanged (passing)
// ---------------------------------------------------------------------------
template<int BM, int BN, int BK, int TM>
__global__ void __launch_bounds__((BM/TM)*(BN/4))
sgemm_pipe(float* __restrict__ C, int ldc,
           const float* __restrict__ A1, int lda1, int K1,
           const float* __restrict__ A2, int lda2, int K2,
           const float* __restrict__ W,  int ldw,
           const float* __restrict__ bias,
           int M, int N, int KC)
{
    constexpr int TN = 4;
    constexpr int THREADS = (BM/TM)*(BN/TN);
    constexpr int BMq = BM/4, BNq = BN/4, BKq = BK/4;
    constexpr int NA = (BM*BKq)/THREADS;
    constexpr int NW = (BN*BKq)/THREADS;

    __shared__ float4 As[2][BK][BMq];
    __shared__ float4 Ws[2][BK][BNq];

    const int tid  = threadIdx.x;
    const int tn   = tid % (BN/TN);
    const int tm   = tid / (BN/TN);
    const int row0 = blockIdx.y * BM;
    const int col0 = blockIdx.x * BN;
    const int K    = K1 + K2;
    const int kbeg = blockIdx.z * KC;
    const int kend = (kbeg + KC < K) ? (kbeg + KC) : K;
    const int ntile = (kend - kbeg) / BK;
    float* Cz = C + (size_t)blockIdx.z * M * N;

    ull acc[TM/2][TN];
#pragma unroll
    for (int i = 0; i < TM/2; ++i)
#pragma unroll
        for (int j = 0; j < TN; ++j) acc[i][j] = 0ULL;

    float4 ra[NA], rw[NW];

    auto LOADT = [&](int t) {
        const int k0 = kbeg + t * BK;
        const float* Ap; int lda; int kk;
        if (k0 < K1) { Ap = A1; lda = lda1; kk = k0; }
        else         { Ap = A2; lda = lda2; kk = k0 - K1; }
#pragma unroll
        for (int i = 0; i < NA; ++i) {
            int idx = tid + i * THREADS;
            int m = idx / BKq, kq = idx % BKq;
            int gm = row0 + m;
            ra[i] = (gm < M)
                ? *reinterpret_cast<const float4*>(Ap + (size_t)gm*lda + kk + kq*4)
                : make_float4(0.f, 0.f, 0.f, 0.f);
        }
#pragma unroll
        for (int i = 0; i < NW; ++i) {
            int idx = tid + i * THREADS;
            int n = idx / BKq, kq = idx % BKq;
            int gn = col0 + n;
            rw[i] = (gn < N)
                ? *reinterpret_cast<const float4*>(W + (size_t)gn*ldw + k0 + kq*4)
                : make_float4(0.f, 0.f, 0.f, 0.f);
        }
    };

    auto STORET = [&](int bsel) {
#pragma unroll
        for (int i = 0; i < NA; ++i) {
            int idx = tid + i * THREADS;
            int m = idx / BKq, kq = idx % BKq;
            const float* pv = reinterpret_cast<const float*>(&ra[i]);
#pragma unroll
            for (int r = 0; r < 4; ++r) {
                int k = kq*4 + r;
                int j = (m >> 2) ^ kq;
                reinterpret_cast<float*>(&As[bsel][k][j])[m & 3] = pv[r];
            }
        }
#pragma unroll
        for (int i = 0; i < NW; ++i) {
            int idx = tid + i * THREADS;
            int n = idx / BKq, kq = idx % BKq;
            const float* pv = reinterpret_cast<const float*>(&rw[i]);
#pragma unroll
            for (int r = 0; r < 4; ++r) {
                int k = kq*4 + r;
                int j = (n >> 2) ^ kq;
                reinterpret_cast<float*>(&Ws[bsel][k][j])[n & 3] = pv[r];
            }
        }
    };

    auto COMP = [&](int bsel) {
#pragma unroll
        for (int k = 0; k < BK; ++k) {
            const int s = (k >> 2) & 7;
            ull a2[TM/2];
#pragma unroll
            for (int q = 0; q < TM/4; ++q) {
                ulonglong2 p = *reinterpret_cast<const ulonglong2*>(
                    &As[bsel][k][(tm*(TM/4) + q) ^ s]);
                a2[2*q]   = p.x;
                a2[2*q+1] = p.y;
            }
            float4 wv = Ws[bsel][k][tn ^ s];
            ull w0 = dup2(wv.x), w1 = dup2(wv.y), w2 = dup2(wv.z), w3 = dup2(wv.w);
#pragma unroll
            for (int i = 0; i < TM/2; ++i) {
                acc[i][0] = ffma2(a2[i], w0, acc[i][0]);
                acc[i][1] = ffma2(a2[i], w1, acc[i][1]);
                acc[i][2] = ffma2(a2[i], w2, acc[i][2]);
                acc[i][3] = ffma2(a2[i], w3, acc[i][3]);
            }
        }
    };

    if (ntile > 0) {
        LOADT(0);
        STORET(0);
        __syncthreads();
        for (int t = 0; t < ntile; ++t) {
            if (t + 1 < ntile) LOADT(t + 1);
            COMP(t & 1);
            if (t + 1 < ntile) {
                __syncthreads();
                STORET((t + 1) & 1);
                __syncthreads();
            }
        }
    }

    const int cc = col0 + tn*TN;
    float bv[TN];
#pragma unroll
    for (int j = 0; j < TN; ++j) {
        int cj = cc + j;
        bv[j] = (bias != nullptr && cj < N) ? bias[cj] : 0.f;
    }
#pragma unroll
    for (int i = 0; i < TM/2; ++i) {
        float2 u[TN];
#pragma unroll
        for (int j = 0; j < TN; ++j) u[j] = unpk(acc[i][j]);
#pragma unroll
        for (int rr = 0; rr < 2; ++rr) {
            int r = row0 + tm*TM + 2*i + rr;
            if (r >= M) continue;
            float vals[TN];
#pragma unroll
            for (int j = 0; j < TN; ++j)
                vals[j] = (rr == 0 ? u[j].x : u[j].y) + bv[j];
            float* cp = Cz + (size_t)r*ldc + cc;
            if (cc + 3 < N) {
                *reinterpret_cast<float4*>(cp) =
                    make_float4(vals[0], vals[1], vals[2], vals[3]);
            } else {
#pragma unroll
                for (int j = 0; j < TN; ++j)
                    if (cc + j < N) cp[j] = vals[j];
            }
        }
    }
}

// ---------------------------------------------------------------------------
// Prep kernels
// ---------------------------------------------------------------------------
__global__ void k_prep(const float* __restrict__ b_ih, const float* __restrict__ b_hh,
                       const float* __restrict__ W_ih, const float* __restrict__ W_hh)
{
    int idx = blockIdx.x * blockDim.x + threadIdx.x;
    int stride = gridDim.x * blockDim.x;
    for (int i = idx; i < B*H; i += stride) {
        g_buf[H_OFF + i] = 0.f;
        g_buf[C_OFF + i] = 0.f;
    }
    for (int i = idx; i < G4; i += stride)
        g_buf[BS_OFF + i] = b_ih[i] + b_hh[i];
    for (int i = idx; i < G4*(E+H); i += stride) {
        int n = i >> 10;
        int k = i & 1023;
        g_buf[WG_OFF + i] = (k < E) ? W_ih[n*E + k] : W_hh[n*H + (k - E)];
    }
}

__global__ void k_build_xs(const float* __restrict__ features,
                           const int*   __restrict__ captions,
                           const float* __restrict__ embed)
{
    int idx = blockIdx.x * blockDim.x + threadIdx.x;
    int stride = gridDim.x * blockDim.x;
    for (int i = idx; i < TP1*B*E; i += stride) {
        int e  = i & (E - 1);
        int be = i >> 9;
        int b  = be & (B - 1);
        int t  = be >> 7;
        float v;
        if (t == 0) {
            v = features[b*E + e];
        } else {
            int tok = captions[b*T + (t - 1)];
            v = embed[(size_t)tok*E + e];
        }
        g_buf[XS_OFF + i] = v;
    }
}

// ---------------------------------------------------------------------------
// softmax(pre + 4 splitK slabs) * cnn -> att
// ---------------------------------------------------------------------------
__global__ void __launch_bounds__(256)
k_softmax_att(const float* __restrict__ pre,
              const float* __restrict__ slab,
              const float* __restrict__ cnn,
              float* __restrict__ att)
{
    int b = blockIdx.x;
    int t = threadIdx.x;
    const size_t o0 = (size_t)b*A;
    const size_t BA = (size_t)B*A;
    float v[8];
    float mx = -1e30f;
#pragma unroll
    for (int i = 0; i < 8; ++i) {
        size_t o = o0 + t + 256*i;
        float s = pre[o] + slab[o] + slab[o + BA] + slab[o + 2*BA] + slab[o + 3*BA];
        v[i] = s;
        mx = fmaxf(mx, s);
    }
    __shared__ float red[256];
    red[t] = mx; __syncthreads();
    for (int off = 128; off > 0; off >>= 1) {
        if (t < off) red[t] = fmaxf(red[t], red[t + off]);
        __syncthreads();
    }
    mx = red[0]; __syncthreads();

    float sum = 0.f;
#pragma unroll
    for (int i = 0; i < 8; ++i) {
        v[i] = expf(v[i] - mx);
        sum += v[i];
    }
    red[t] = sum; __syncthreads();
    for (int off = 128; off > 0; off >>= 1) {
        if (t < off) red[t] += red[t + off];
        __syncthreads();
    }
    float inv = 1.f / red[0];

    const float* cb = cnn + o0;
    float* ab = att + o0;
#pragma unroll
    for (int i = 0; i < 8; ++i)
        ab[t + 256*i] = cb[t + 256*i] * v[i] * inv;
}

__global__ void k_reduce_attd(const float* __restrict__ pre,
                              const float* __restrict__ slab,
                              float* __restrict__ x2)
{
    int i = blockIdx.x * blockDim.x + threadIdx.x;
    if (i < B*E) {
        float s = pre[i];
#pragma unroll
        for (int z = 0; z < 8; ++z) s += slab[i + (size_t)z*B*E];
        x2[i] = s;
    }
}

__global__ void k_lstm_red(const float* __restrict__ sl,
                           const float* __restrict__ bsum,
                           float* __restrict__ h, float* __restrict__ c,
                           float* __restrict__ hid)
{
    int idx = blockIdx.x * blockDim.x + threadIdx.x;
    if (idx >= B*H) return;
    int b = idx >> 9;
    int j = idx & (H - 1);
    float gi = bsum[j], gf = bsum[j + H], gg = bsum[j + 2*H], go = bsum[j + 3*H];
#pragma unroll
    for (int z = 0; z < 4; ++z) {
        const float* g = sl + (size_t)z*B*G4 + (size_t)b*G4;
        gi += g[j]; gf += g[j + H]; gg += g[j + 2*H]; go += g[j + 3*H];
    }
    float ig = 1.f / (1.f + expf(-gi));
    float fg = 1.f / (1.f + expf(-gf));
    float gt = tanhf(gg);
    float og = 1.f / (1.f + expf(-go));
    float cn = fg * c[idx] + ig * gt;
    float hn = og * tanhf(cn);
    c[idx] = cn;
    h[idx] = hn;
    hid[idx] = hn;
}

// ---------------------------------------------------------------------------
// Host launch sequence (graph-capturable: kernel launches only)
// ---------------------------------------------------------------------------
extern "C" void kernel_launch(void* const* d_in, const int* in_sizes, int n_in,
                              void* d_out, int out_size)
{
    const float* features = (const float*)d_in[0];
    const float* cnn      = (const float*)d_in[1];
    const int*   captions = (const int*)  d_in[2];
    /* d_in[3] = lengths (unused: all T+1) */
    const float* embed    = (const float*)d_in[4];
    const float* W_ih     = (const float*)d_in[5];
    const float* W_hh     = (const float*)d_in[6];
    const float* b_ih     = (const float*)d_in[7];
    const float* b_hh     = (const float*)d_in[8];
    const float* W_attn   = (const float*)d_in[9];
    const float* b_attn   = (const float*)d_in[10];
    const float* W_attd   = (const float*)d_in[11];
    const float* b_attd   = (const float*)d_in[12];
    const float* W_out    = (const float*)d_in[13];
    const float* b_out    = (const float*)d_in[14];
    float* out = (float*)d_out;

    float* buf = nullptr;
    cudaGetSymbolAddress((void**)&buf, g_buf);
    __nv_bfloat16 *xs_bf, *hid_bf, *wattn_bf, *wattd_bf, *wout_bf;
    cudaGetSymbolAddress((void**)&xs_bf,    g_xs_bf);
    cudaGetSymbolAddress((void**)&hid_bf,   g_hid_bf);
    cudaGetSymbolAddress((void**)&wattn_bf, g_wattn_bf);
    cudaGetSymbolAddress((void**)&wattd_bf, g_wattd_bf);
    cudaGetSymbolAddress((void**)&wout_bf,  g_wout_bf);

    float* xs    = buf + XS_OFF;
    float* pan   = buf + PAN_OFF;
    float* pad   = buf + PAD_OFF;
    float* hid   = buf + HID_OFF;
    float* hbuf  = buf + H_OFF;
    float* cbuf  = buf + C_OFF;
    float* att   = buf + ATT_OFF;
    float* x2    = buf + X2_OFF;
    float* slA   = buf + SLA_OFF;
    float* slD   = buf + SLD_OFF;
    float* slG   = buf + SLG_OFF;
    float* Wg    = buf + WG_OFF;
    float* bsum  = buf + BS_OFF;

    // prep
    k_prep<<<2048, 256>>>(b_ih, b_hh, W_ih, W_hh);
    k_build_xs<<<2048, 256>>>(features, captions, embed);

    // split-bf16 conversions
    k_split_a<<<4096, 256>>>(xs, xs_bf, MALL);
    k_split_b<<<2048, 256>>>(W_attn, E + H, wattn_bf, A, A);
    k_split_b<<<1024, 256>>>(W_attd, E + A, wattd_bf, E, E);
    k_split_b<<<8192, 256>>>(W_out,  H,     wout_bf,  V, VPAD);

    // pan[t] = x_t @ W_attn[:, :E]^T + b_attn  (HMMA bf16 3-term split)
    hmma_gemm<<<dim3(A / 128, MALL / 128), 256>>>(
        pan, A, A, xs_bf, wattn_bf, b_attn);
    // pad[t] = x_t @ W_attd[:, :E]^T + b_attd
    hmma_gemm<<<dim3(E / 128, MALL / 128), 256>>>(
        pad, E, E, xs_bf, wattd_bf, b_attd);

    const dim3 gGate(G4/64, B/32, 4);
    const dim3 gAttn(A /64, B/32, 4);
    const dim3 gAttd(E /64, B/32, 8);

    // t = 0
    sgemm_pipe<32, 64, 32, 4><<<gGate, 128>>>(
        slG, G4, xs, E, E, hbuf, H, H, Wg, E + H, nullptr, B, G4, (E + H)/4);
    k_lstm_red<<<(B*H + 255)/256, 256>>>(slG, bsum, hbuf, cbuf, hid);

    // t = 1..T
    for (int t = 1; t <= T; ++t) {
        sgemm_pipe<32, 64, 32, 4><<<gAttn, 128>>>(
            slA, A, hbuf, H, H, nullptr, 0, 0, W_attn + E, E + H, nullptr,
            B, A, H/4);
        k_softmax_att<<<B, 256>>>(pan + (size_t)t*B*A, slA, cnn, att);
        sgemm_pipe<32, 64, 32, 4><<<gAttd, 128>>>(
            slD, E, att, A, A, nullptr, 0, 0, W_attd + E, E + A, nullptr,
            B, E, A/8);
        k_reduce_attd<<<(B*E + 255)/256, 256>>>(pad + (size_t)t*B*E, slD, x2);
        sgemm_pipe<32, 64, 32, 4><<<gGate, 128>>>(
            slG, G4, x2, E, E, hbuf, H, H, Wg, E + H, nullptr, B, G4, (E + H)/4);
        k_lstm_red<<<(B*H + 255)/256, 256>>>(slG, bsum, hbuf, cbuf,
                                             hid + (size_t)t*B*H);
    }

    // logits = hidden @ W_out^T + b_out  (HMMA bf16 3-term split)
    k_split_a<<<4096, 256>>>(hid, hid_bf, MALL);
    hmma_gemm<<<dim3(VPAD / 128, MALL / 128), 256>>>(
        out, V, V, hid_bf, wout_bf, b_out);
}

// round 6
// speedup vs baseline: 3.3307x; 1.0774x over previous
#include <cuda_runtime.h>
#include <cuda_bf16.h>
#include <cuda_fp16.h>
#include <math.h>
#include <stdint.h>

// ---------------------------------------------------------------------------
// Problem constants
// ---------------------------------------------------------------------------
namespace {
constexpr int B   = 128;
constexpr int T   = 31;
constexpr int TP1 = 32;     // T+1
constexpr int E   = 512;
constexpr int H   = 512;
constexpr int V   = 10000;
constexpr int A   = 2048;
constexpr int G4  = 2048;   // 4*H
constexpr int MALL = TP1 * B;   // 4096
constexpr int VPAD = 10240;     // 80 * 128
constexpr int KBF  = 1536;      // 3 * 512 split-bf16 K (pan/pad)
constexpr int KHF  = 1024;      // 2 * 512 split-fp16 K (logits)

// scratch layout (floats) inside one __device__ buffer
constexpr size_t XS_OFF   = 0;                              // [TP1][B][E]
constexpr size_t PAN_OFF  = XS_OFF  + (size_t)TP1*B*E;      // [TP1][B][A]
constexpr size_t PAD_OFF  = PAN_OFF + (size_t)TP1*B*A;      // [TP1][B][E]
constexpr size_t H_OFF    = PAD_OFF + (size_t)TP1*B*E;      // [B][H]
constexpr size_t C_OFF    = H_OFF   + (size_t)B*H;          // [B][H]
constexpr size_t ATT_OFF  = C_OFF   + (size_t)B*H;          // [B][A]
constexpr size_t X2_OFF   = ATT_OFF + (size_t)B*A;          // [B][E]
constexpr size_t SLA_OFF  = X2_OFF  + (size_t)B*E;          // [4][B][A]
constexpr size_t SLD_OFF  = SLA_OFF + (size_t)4*B*A;        // [8][B][E]
constexpr size_t SLG_OFF  = SLD_OFF + (size_t)8*B*E;        // [4][B][G4]
constexpr size_t WG_OFF   = SLG_OFF + (size_t)4*B*G4;       // [G4][E+H]
constexpr size_t BS_OFF   = WG_OFF  + (size_t)G4*(E+H);     // [G4]
constexpr size_t BUF_TOTAL = BS_OFF + (size_t)G4;
}

__device__ float g_buf[BUF_TOTAL];

// bf16 split operand buffers (pan/pad: 3-term)
__device__ __nv_bfloat16 g_xs_bf [(size_t)MALL * KBF];
__device__ __nv_bfloat16 g_wattn_bf[(size_t)A * KBF];
__device__ __nv_bfloat16 g_wattd_bf[(size_t)E * KBF];
// fp16 split operand buffers (logits: 2-term)
__device__ __half g_hid_h [(size_t)MALL * KHF];
__device__ __half g_wout_h[(size_t)VPAD * KHF];

// ---------------------------------------------------------------------------
// Packed f32x2 FMA helpers (sm_103a; legal PTX for compute_103)
// ---------------------------------------------------------------------------
typedef unsigned long long ull;

__device__ __forceinline__ ull ffma2(ull a, ull b, ull c) {
    ull d;
    asm("fma.rn.f32x2 %0, %1, %2, %3;" : "=l"(d) : "l"(a), "l"(b), "l"(c));
    return d;
}
__device__ __forceinline__ ull dup2(float x) {
    ull d;
    asm("mov.b64 %0, {%1, %1};" : "=l"(d) : "f"(x));
    return d;
}
__device__ __forceinline__ float2 unpk(ull v) {
    float2 r;
    asm("mov.b64 {%0, %1}, %2;" : "=f"(r.x), "=f"(r.y) : "l"(v));
    return r;
}

// ---------------------------------------------------------------------------
// HMMA helpers (sm_80+ PTX — compiles for compute_103)
// ---------------------------------------------------------------------------
__device__ __forceinline__ uint32_t smem_u32(const void* p) {
    uint32_t a;
    asm("{ .reg .u64 t; cvta.to.shared.u64 t, %1; cvt.u32.u64 %0, t; }"
        : "=r"(a) : "l"(p));
    return a;
}
__device__ __forceinline__ void cpa16(uint32_t s, const void* g) {
    asm volatile("cp.async.cg.shared.global [%0], [%1], 16;"
                 :: "r"(s), "l"(g));
}
#define CP_COMMIT() asm volatile("cp.async.commit_group;" ::: "memory")
#define CP_WAIT(N)  asm volatile("cp.async.wait_group %0;" :: "n"(N) : "memory")

#define LDSM4(R0, R1, R2, R3, ADDR) \
    asm volatile("ldmatrix.sync.aligned.m8n8.x4.shared.b16 {%0,%1,%2,%3}, [%4];" \
        : "=r"(R0), "=r"(R1), "=r"(R2), "=r"(R3) : "r"(ADDR))

template<bool FP16>
__device__ __forceinline__ void mma16816(float* d, const uint32_t* a,
                                         uint32_t b0, uint32_t b1) {
    if constexpr (FP16) {
        asm volatile(
            "mma.sync.aligned.m16n8k16.row.col.f32.f16.f16.f32 "
            "{%0,%1,%2,%3}, {%4,%5,%6,%7}, {%8,%9}, {%0,%1,%2,%3};"
            : "+f"(d[0]), "+f"(d[1]), "+f"(d[2]), "+f"(d[3])
            : "r"(a[0]), "r"(a[1]), "r"(a[2]), "r"(a[3]), "r"(b0), "r"(b1));
    } else {
        asm volatile(
            "mma.sync.aligned.m16n8k16.row.col.f32.bf16.bf16.f32 "
            "{%0,%1,%2,%3}, {%4,%5,%6,%7}, {%8,%9}, {%0,%1,%2,%3};"
            : "+f"(d[0]), "+f"(d[1]), "+f"(d[2]), "+f"(d[3])
            : "r"(a[0]), "r"(a[1]), "r"(a[2]), "r"(a[3]), "r"(b0), "r"(b1));
    }
}

// ---------------------------------------------------------------------------
// HMMA GEMM: C[M][Nreal] (+bias) = Abf[M][KTOT] @ Bbf[Npad][KTOT]^T
// 16-bit elems (bf16 or fp16 per FP16 flag). M, Npad multiples of 128.
// 128x128x32 tile, 256 threads, 3-stage cp.async circular pipeline,
// 80B-padded smem rows, dynamic shared memory (3 x 20480 B).
// ---------------------------------------------------------------------------
namespace {
constexpr int HBK   = 32;
constexpr int HROWB = 80;            // 32 elems * 2B + 16B pad
constexpr int HSTG  = 256 * HROWB;   // 20480 B per stage (A 128 + B 128 rows)
constexpr int HSMEM = 3 * HSTG;      // 61440 B
}

template<int KTOT, bool FP16>
__global__ void __launch_bounds__(256, 2)
hmma_gemm(float* __restrict__ C, int ldc, int Nreal,
          const uint16_t* __restrict__ Abf,
          const uint16_t* __restrict__ Bbf,
          const float* __restrict__ bias)
{
    constexpr int NT = KTOT / HBK;
    extern __shared__ __align__(16) char sm[];
    const uint32_t sb = smem_u32(sm);

    const int tid  = threadIdx.x;
    const int wid  = tid >> 5;
    const int lane = tid & 31;
    const int wm   = wid & 1;        // 2 warp rows (64 rows each)
    const int wn   = wid >> 1;       // 4 warp cols (32 cols each)
    const int row0 = blockIdx.y * 128;
    const int col0 = blockIdx.x * 128;

    // per-thread cp.async assignment: 2 A chunks + 2 B chunks of 16B
    const int qr0 = (tid)       >> 2, qc0 = (tid)       & 3;
    const int qr1 = (tid + 256) >> 2, qc1 = (tid + 256) & 3;

    auto LOADG = [&](int t, int stg) {
        const int k0 = t * HBK;
        const uint32_t sa  = sb + stg * HSTG;
        const uint32_t sbm = sa + 128 * HROWB;
        cpa16(sa  + qr0 * HROWB + qc0 * 16,
              Abf + (size_t)(row0 + qr0) * KTOT + k0 + qc0 * 8);
        cpa16(sa  + qr1 * HROWB + qc1 * 16,
              Abf + (size_t)(row0 + qr1) * KTOT + k0 + qc1 * 8);
        cpa16(sbm + qr0 * HROWB + qc0 * 16,
              Bbf + (size_t)(col0 + qr0) * KTOT + k0 + qc0 * 8);
        cpa16(sbm + qr1 * HROWB + qc1 * 16,
              Bbf + (size_t)(col0 + qr1) * KTOT + k0 + qc1 * 8);
    };

    float acc[4][4][4];
#pragma unroll
    for (int i = 0; i < 4; ++i)
#pragma unroll
        for (int j = 0; j < 4; ++j)
#pragma unroll
            for (int q = 0; q < 4; ++q) acc[i][j][q] = 0.f;

    const int lr  = lane & 15;           // row within 16
    const int lkb = (lane >> 4) * 16;    // byte offset of 8-elem k chunk

    LOADG(0, 0); CP_COMMIT();
    LOADG(1, 1); CP_COMMIT();

    for (int t = 0; t < NT; ++t) {
        if (t + 1 < NT) { CP_WAIT(1); } else { CP_WAIT(0); }
        __syncthreads();
        if (t + 2 < NT) { LOADG(t + 2, (t + 2) % 3); CP_COMMIT(); }

        const uint32_t aB = sb + (t % 3) * HSTG;
        const uint32_t bB = aB + 128 * HROWB;
#pragma unroll
        for (int ks = 0; ks < 2; ++ks) {
            const int kbyte = ks * 32 + lkb;
            uint32_t af[4][4];
#pragma unroll
            for (int mf = 0; mf < 4; ++mf)
                LDSM4(af[mf][0], af[mf][1], af[mf][2], af[mf][3],
                      aB + (wm * 64 + mf * 16 + lr) * HROWB + kbyte);
            uint32_t bfr[2][4];
#pragma unroll
            for (int p = 0; p < 2; ++p)
                LDSM4(bfr[p][0], bfr[p][1], bfr[p][2], bfr[p][3],
                      bB + (wn * 32 + p * 16 + lr) * HROWB + kbyte);
#pragma unroll
            for (int mf = 0; mf < 4; ++mf)
#pragma unroll
                for (int nf = 0; nf < 4; ++nf)
                    mma16816<FP16>(acc[mf][nf], af[mf],
                                   bfr[nf >> 1][nf & 1], bfr[nf >> 1][(nf & 1) + 2]);
        }
    }

    // epilogue: direct stores + bias
    const int rbase = row0 + wm * 64 + (lane >> 2);
    const int cbase = col0 + wn * 32 + 2 * (lane & 3);
#pragma unroll
    for (int nf = 0; nf < 4; ++nf) {
        const int col = cbase + nf * 8;
        if (col >= Nreal) continue;
        const float2 bv = *reinterpret_cast<const float2*>(bias + col);
#pragma unroll
        for (int mf = 0; mf < 4; ++mf) {
            const int r = rbase + mf * 16;
            *reinterpret_cast<float2*>(C + (size_t)r * ldc + col) =
                make_float2(acc[mf][nf][0] + bv.x, acc[mf][nf][1] + bv.y);
            *reinterpret_cast<float2*>(C + (size_t)(r + 8) * ldc + col) =
                make_float2(acc[mf][nf][2] + bv.x, acc[mf][nf][3] + bv.y);
        }
    }
}

// ---------------------------------------------------------------------------
// Conversion kernels
// ---------------------------------------------------------------------------
// bf16 3-term, A side: [hi | hi | lo]
__global__ void k_split_a(const float* __restrict__ src,
                          __nv_bfloat16* __restrict__ dst, int M)
{
    int i = blockIdx.x * blockDim.x + threadIdx.x;
    int n = M * 512;
    for (; i < n; i += gridDim.x * blockDim.x) {
        int m = i >> 9, j = i & 511;
        float x = src[i];
        __nv_bfloat16 hi = __float2bfloat16(x);
        __nv_bfloat16 lo = __float2bfloat16(x - __bfloat162float(hi));
        __nv_bfloat16* d = dst + (size_t)m * KBF;
        d[j] = hi; d[j + 512] = hi; d[j + 1024] = lo;
    }
}

// bf16 3-term, B side: [hi | lo | hi]
__global__ void k_split_b(const float* __restrict__ src, int ld,
                          __nv_bfloat16* __restrict__ dst, int Nreal, int Npad)
{
    int i = blockIdx.x * blockDim.x + threadIdx.x;
    int n = Npad * 512;
    for (; i < n; i += gridDim.x * blockDim.x) {
        int r = i >> 9, j = i & 511;
        float x = (r < Nreal) ? src[(size_t)r * ld + j] : 0.f;
        __nv_bfloat16 hi = __float2bfloat16(x);
        __nv_bfloat16 lo = __float2bfloat16(x - __bfloat162float(hi));
        __nv_bfloat16* d = dst + (size_t)r * KBF;
        d[j] = hi; d[j + 512] = lo; d[j + 1024] = hi;
    }
}

// fp16 2-term, B side (W_out): [hi | hi]
__global__ void k_split_b16(const float* __restrict__ src, int ld,
                            __half* __restrict__ dst, int Nreal, int Npad)
{
    int i = blockIdx.x * blockDim.x + threadIdx.x;
    int n = Npad * 512;
    for (; i < n; i += gridDim.x * blockDim.x) {
        int r = i >> 9, j = i & 511;
        float x = (r < Nreal) ? src[(size_t)r * ld + j] : 0.f;
        __half hi = __float2half(x);
        __half* d = dst + (size_t)r * KHF;
        d[j] = hi; d[j + 512] = hi;
    }
}

// ---------------------------------------------------------------------------
// Pipelined dual-input fp32 SGEMM (recurrent path) — unchanged (passing)
// ---------------------------------------------------------------------------
template<int BM, int BN, int BK, int TM>
__global__ void __launch_bounds__((BM/TM)*(BN/4))
sgemm_pipe(float* __restrict__ C, int ldc,
           const float* __restrict__ A1, int lda1, int K1,
           const float* __restrict__ A2, int lda2, int K2,
           const float* __restrict__ W,  int ldw,
           const float* __restrict__ bias,
           int M, int N, int KC)
{
    constexpr int TN = 4;
    constexpr int THREADS = (BM/TM)*(BN/TN);
    constexpr int BMq = BM/4, BNq = BN/4, BKq = BK/4;
    constexpr int NA = (BM*BKq)/THREADS;
    constexpr int NW = (BN*BKq)/THREADS;

    __shared__ float4 As[2][BK][BMq];
    __shared__ float4 Ws[2][BK][BNq];

    const int tid  = threadIdx.x;
    const int tn   = tid % (BN/TN);
    const int tm   = tid / (BN/TN);
    const int row0 = blockIdx.y * BM;
    const int col0 = blockIdx.x * BN;
    const int K    = K1 + K2;
    const int kbeg = blockIdx.z * KC;
    const int kend = (kbeg + KC < K) ? (kbeg + KC) : K;
    const int ntile = (kend - kbeg) / BK;
    float* Cz = C + (size_t)blockIdx.z * M * N;

    ull acc[TM/2][TN];
#pragma unroll
    for (int i = 0; i < TM/2; ++i)
#pragma unroll
        for (int j = 0; j < TN; ++j) acc[i][j] = 0ULL;

    float4 ra[NA], rw[NW];

    auto LOADT = [&](int t) {
        const int k0 = kbeg + t * BK;
        const float* Ap; int lda; int kk;
        if (k0 < K1) { Ap = A1; lda = lda1; kk = k0; }
        else         { Ap = A2; lda = lda2; kk = k0 - K1; }
#pragma unroll
        for (int i = 0; i < NA; ++i) {
            int idx = tid + i * THREADS;
            int m = idx / BKq, kq = idx % BKq;
            int gm = row0 + m;
            ra[i] = (gm < M)
                ? *reinterpret_cast<const float4*>(Ap + (size_t)gm*lda + kk + kq*4)
                : make_float4(0.f, 0.f, 0.f, 0.f);
        }
#pragma unroll
        for (int i = 0; i < NW; ++i) {
            int idx = tid + i * THREADS;
            int n = idx / BKq, kq = idx % BKq;
            int gn = col0 + n;
            rw[i] = (gn < N)
                ? *reinterpret_cast<const float4*>(W + (size_t)gn*ldw + k0 + kq*4)
                : make_float4(0.f, 0.f, 0.f, 0.f);
        }
    };

    auto STORET = [&](int bsel) {
#pragma unroll
        for (int i = 0; i < NA; ++i) {
            int idx = tid + i * THREADS;
            int m = idx / BKq, kq = idx % BKq;
            const float* pv = reinterpret_cast<const float*>(&ra[i]);
#pragma unroll
            for (int r = 0; r < 4; ++r) {
                int k = kq*4 + r;
                int j = (m >> 2) ^ kq;
                reinterpret_cast<float*>(&As[bsel][k][j])[m & 3] = pv[r];
            }
        }
#pragma unroll
        for (int i = 0; i < NW; ++i) {
            int idx = tid + i * THREADS;
            int n = idx / BKq, kq = idx % BKq;
            const float* pv = reinterpret_cast<const float*>(&rw[i]);
#pragma unroll
            for (int r = 0; r < 4; ++r) {
                int k = kq*4 + r;
                int j = (n >> 2) ^ kq;
                reinterpret_cast<float*>(&Ws[bsel][k][j])[n & 3] = pv[r];
            }
        }
    };

    auto COMP = [&](int bsel) {
#pragma unroll
        for (int k = 0; k < BK; ++k) {
            const int s = (k >> 2) & 7;
            ull a2[TM/2];
#pragma unroll
            for (int q = 0; q < TM/4; ++q) {
                ulonglong2 p = *reinterpret_cast<const ulonglong2*>(
                    &As[bsel][k][(tm*(TM/4) + q) ^ s]);
                a2[2*q]   = p.x;
                a2[2*q+1] = p.y;
            }
            float4 wv = Ws[bsel][k][tn ^ s];
            ull w0 = dup2(wv.x), w1 = dup2(wv.y), w2 = dup2(wv.z), w3 = dup2(wv.w);
#pragma unroll
            for (int i = 0; i < TM/2; ++i) {
                acc[i][0] = ffma2(a2[i], w0, acc[i][0]);
                acc[i][1] = ffma2(a2[i], w1, acc[i][1]);
                acc[i][2] = ffma2(a2[i], w2, acc[i][2]);
                acc[i][3] = ffma2(a2[i], w3, acc[i][3]);
            }
        }
    };

    if (ntile > 0) {
        LOADT(0);
        STORET(0);
        __syncthreads();
        for (int t = 0; t < ntile; ++t) {
            if (t + 1 < ntile) LOADT(t + 1);
            COMP(t & 1);
            if (t + 1 < ntile) {
                __syncthreads();
                STORET((t + 1) & 1);
                __syncthreads();
            }
        }
    }

    const int cc = col0 + tn*TN;
    float bv[TN];
#pragma unroll
    for (int j = 0; j < TN; ++j) {
        int cj = cc + j;
        bv[j] = (bias != nullptr && cj < N) ? bias[cj] : 0.f;
    }
#pragma unroll
    for (int i = 0; i < TM/2; ++i) {
        float2 u[TN];
#pragma unroll
        for (int j = 0; j < TN; ++j) u[j] = unpk(acc[i][j]);
#pragma unroll
        for (int rr = 0; rr < 2; ++rr) {
            int r = row0 + tm*TM + 2*i + rr;
            if (r >= M) continue;
            float vals[TN];
#pragma unroll
            for (int j = 0; j < TN; ++j)
                vals[j] = (rr == 0 ? u[j].x : u[j].y) + bv[j];
            float* cp = Cz + (size_t)r*ldc + cc;
            if (cc + 3 < N) {
                *reinterpret_cast<float4*>(cp) =
                    make_float4(vals[0], vals[1], vals[2], vals[3]);
            } else {
#pragma unroll
                for (int j = 0; j < TN; ++j)
                    if (cc + j < N) cp[j] = vals[j];
            }
        }
    }
}

// ---------------------------------------------------------------------------
// Prep kernels
// ---------------------------------------------------------------------------
__global__ void k_prep(const float* __restrict__ b_ih, const float* __restrict__ b_hh,
                       const float* __restrict__ W_ih, const float* __restrict__ W_hh)
{
    int idx = blockIdx.x * blockDim.x + threadIdx.x;
    int stride = gridDim.x * blockDim.x;
    for (int i = idx; i < B*H; i += stride) {
        g_buf[H_OFF + i] = 0.f;
        g_buf[C_OFF + i] = 0.f;
    }
    for (int i = idx; i < G4; i += stride)
        g_buf[BS_OFF + i] = b_ih[i] + b_hh[i];
    for (int i = idx; i < G4*(E+H); i += stride) {
        int n = i >> 10;
        int k = i & 1023;
        g_buf[WG_OFF + i] = (k < E) ? W_ih[n*E + k] : W_hh[n*H + (k - E)];
    }
}

__global__ void k_build_xs(const float* __restrict__ features,
                           const int*   __restrict__ captions,
                           const float* __restrict__ embed)
{
    int idx = blockIdx.x * blockDim.x + threadIdx.x;
    int stride = gridDim.x * blockDim.x;
    for (int i = idx; i < TP1*B*E; i += stride) {
        int e  = i & (E - 1);
        int be = i >> 9;
        int b  = be & (B - 1);
        int t  = be >> 7;
        float v;
        if (t == 0) {
            v = features[b*E + e];
        } else {
            int tok = captions[b*T + (t - 1)];
            v = embed[(size_t)tok*E + e];
        }
        g_buf[XS_OFF + i] = v;
    }
}

// ---------------------------------------------------------------------------
// softmax(pre + 4 splitK slabs) * cnn -> att
// ---------------------------------------------------------------------------
__global__ void __launch_bounds__(256)
k_softmax_att(const float* __restrict__ pre,
              const float* __restrict__ slab,
              const float* __restrict__ cnn,
              float* __restrict__ att)
{
    int b = blockIdx.x;
    int t = threadIdx.x;
    const size_t o0 = (size_t)b*A;
    const size_t BA = (size_t)B*A;
    float v[8];
    float mx = -1e30f;
#pragma unroll
    for (int i = 0; i < 8; ++i) {
        size_t o = o0 + t + 256*i;
        float s = pre[o] + slab[o] + slab[o + BA] + slab[o + 2*BA] + slab[o + 3*BA];
        v[i] = s;
        mx = fmaxf(mx, s);
    }
    __shared__ float red[256];
    red[t] = mx; __syncthreads();
    for (int off = 128; off > 0; off >>= 1) {
        if (t < off) red[t] = fmaxf(red[t], red[t + off]);
        __syncthreads();
    }
    mx = red[0]; __syncthreads();

    float sum = 0.f;
#pragma unroll
    for (int i = 0; i < 8; ++i) {
        v[i] = expf(v[i] - mx);
        sum += v[i];
    }
    red[t] = sum; __syncthreads();
    for (int off = 128; off > 0; off >>= 1) {
        if (t < off) red[t] += red[t + off];
        __syncthreads();
    }
    float inv = 1.f / red[0];

    const float* cb = cnn + o0;
    float* ab = att + o0;
#pragma unroll
    for (int i = 0; i < 8; ++i)
        ab[t + 256*i] = cb[t + 256*i] * v[i] * inv;
}

__global__ void k_reduce_attd(const float* __restrict__ pre,
                              const float* __restrict__ slab,
                              float* __restrict__ x2)
{
    int i = blockIdx.x * blockDim.x + threadIdx.x;
    if (i < B*E) {
        float s = pre[i];
#pragma unroll
        for (int z = 0; z < 8; ++z) s += slab[i + (size_t)z*B*E];
        x2[i] = s;
    }
}

// LSTM pointwise + 4-slab reduction + bias; h also written as split-fp16 into
// the hidden operand buffer for the logits GEMM (row = t*B + b).
__global__ void k_lstm_red(const float* __restrict__ sl,
                           const float* __restrict__ bsum,
                           float* __restrict__ h, float* __restrict__ c,
                           __half* __restrict__ hid16)
{
    int idx = blockIdx.x * blockDim.x + threadIdx.x;
    if (idx >= B*H) return;
    int b = idx >> 9;
    int j = idx & (H - 1);
    float gi = bsum[j], gf = bsum[j + H], gg = bsum[j + 2*H], go = bsum[j + 3*H];
#pragma unroll
    for (int z = 0; z < 4; ++z) {
        const float* g = sl + (size_t)z*B*G4 + (size_t)b*G4;
        gi += g[j]; gf += g[j + H]; gg += g[j + 2*H]; go += g[j + 3*H];
    }
    float ig = 1.f / (1.f + expf(-gi));
    float fg = 1.f / (1.f + expf(-gf));
    float gt = tanhf(gg);
    float og = 1.f / (1.f + expf(-go));
    float cn = fg * c[idx] + ig * gt;
    float hn = og * tanhf(cn);
    c[idx] = cn;
    h[idx] = hn;
    __half hi = __float2half(hn);
    __half lo = __float2half(hn - __half2float(hi));
    __half* d = hid16 + (size_t)b * KHF;
    d[j] = hi; d[j + 512] = lo;
}

// ---------------------------------------------------------------------------
// Host launch sequence (graph-capturable: kernel launches only)
// ---------------------------------------------------------------------------
extern "C" void kernel_launch(void* const* d_in, const int* in_sizes, int n_in,
                              void* d_out, int out_size)
{
    const float* features = (const float*)d_in[0];
    const float* cnn      = (const float*)d_in[1];
    const int*   captions = (const int*)  d_in[2];
    /* d_in[3] = lengths (unused: all T+1) */
    const float* embed    = (const float*)d_in[4];
    const float* W_ih     = (const float*)d_in[5];
    const float* W_hh     = (const float*)d_in[6];
    const float* b_ih     = (const float*)d_in[7];
    const float* b_hh     = (const float*)d_in[8];
    const float* W_attn   = (const float*)d_in[9];
    const float* b_attn   = (const float*)d_in[10];
    const float* W_attd   = (const float*)d_in[11];
    const float* b_attd   = (const float*)d_in[12];
    const float* W_out    = (const float*)d_in[13];
    const float* b_out    = (const float*)d_in[14];
    float* out = (float*)d_out;

    float* buf = nullptr;
    cudaGetSymbolAddress((void**)&buf, g_buf);
    __nv_bfloat16 *xs_bf, *wattn_bf, *wattd_bf;
    __half *hid_h, *wout_h;
    cudaGetSymbolAddress((void**)&xs_bf,    g_xs_bf);
    cudaGetSymbolAddress((void**)&wattn_bf, g_wattn_bf);
    cudaGetSymbolAddress((void**)&wattd_bf, g_wattd_bf);
    cudaGetSymbolAddress((void**)&hid_h,    g_hid_h);
    cudaGetSymbolAddress((void**)&wout_h,   g_wout_h);

    static bool attr_done = false;
    if (!attr_done) {
        cudaFuncSetAttribute(hmma_gemm<KBF, false>,
                             cudaFuncAttributeMaxDynamicSharedMemorySize, HSMEM);
        cudaFuncSetAttribute(hmma_gemm<KHF, true>,
                             cudaFuncAttributeMaxDynamicSharedMemorySize, HSMEM);
        attr_done = true;
    }

    float* xs    = buf + XS_OFF;
    float* pan   = buf + PAN_OFF;
    float* pad   = buf + PAD_OFF;
    float* hbuf  = buf + H_OFF;
    float* cbuf  = buf + C_OFF;
    float* att   = buf + ATT_OFF;
    float* x2    = buf + X2_OFF;
    float* slA   = buf + SLA_OFF;
    float* slD   = buf + SLD_OFF;
    float* slG   = buf + SLG_OFF;
    float* Wg    = buf + WG_OFF;
    float* bsum  = buf + BS_OFF;

    // prep
    k_prep<<<2048, 256>>>(b_ih, b_hh, W_ih, W_hh);
    k_build_xs<<<2048, 256>>>(features, captions, embed);

    // conversions
    k_split_a<<<4096, 256>>>(xs, xs_bf, MALL);
    k_split_b<<<2048, 256>>>(W_attn, E + H, wattn_bf, A, A);
    k_split_b<<<1024, 256>>>(W_attd, E + A, wattd_bf, E, E);
    k_split_b16<<<8192, 256>>>(W_out, H, wout_h, V, VPAD);

    // pan[t] = x_t @ W_attn[:, :E]^T + b_attn  (bf16 3-term)
    hmma_gemm<KBF, false><<<dim3(A / 128, MALL / 128), 256, HSMEM>>>(
        pan, A, A, (const uint16_t*)xs_bf, (const uint16_t*)wattn_bf, b_attn);
    // pad[t] = x_t @ W_attd[:, :E]^T + b_attd  (bf16 3-term)
    hmma_gemm<KBF, false><<<dim3(E / 128, MALL / 128), 256, HSMEM>>>(
        pad, E, E, (const uint16_t*)xs_bf, (const uint16_t*)wattd_bf, b_attd);

    const dim3 gGate(G4/64, B/32, 4);
    const dim3 gAttn(A /64, B/32, 4);
    const dim3 gAttd(E /64, B/32, 8);

    // t = 0
    sgemm_pipe<32, 64, 32, 4><<<gGate, 128>>>(
        slG, G4, xs, E, E, hbuf, H, H, Wg, E + H, nullptr, B, G4, (E + H)/4);
    k_lstm_red<<<(B*H + 255)/256, 256>>>(slG, bsum, hbuf, cbuf, hid_h);

    // t = 1..T
    for (int t = 1; t <= T; ++t) {
        sgemm_pipe<32, 64, 32, 4><<<gAttn, 128>>>(
            slA, A, hbuf, H, H, nullptr, 0, 0, W_attn + E, E + H, nullptr,
            B, A, H/4);
        k_softmax_att<<<B, 256>>>(pan + (size_t)t*B*A, slA, cnn, att);
        sgemm_pipe<32, 64, 32, 4><<<gAttd, 128>>>(
            slD, E, att, A, A, nullptr, 0, 0, W_attd + E, E + A, nullptr,
            B, E, A/8);
        k_reduce_attd<<<(B*E + 255)/256, 256>>>(pad + (size_t)t*B*E, slD, x2);
        sgemm_pipe<32, 64, 32, 4><<<gGate, 128>>>(
            slG, G4, x2, E, E, hbuf, H, H, Wg, E + H, nullptr, B, G4, (E + H)/4);
        k_lstm_red<<<(B*H + 255)/256, 256>>>(slG, bsum, hbuf, cbuf,
                                             hid_h + (size_t)t*B*KHF);
    }

    // logits = hidden @ W_out^T + b_out  (fp16 2-term, K=1024)
    hmma_gemm<KHF, true><<<dim3(VPAD / 128, MALL / 128), 256, HSMEM>>>(
        out, V, V, (const uint16_t*)hid_h, (const uint16_t*)wout_h, b_out);
}